// round 2
// baseline (speedup 1.0000x reference)
#include <cuda_runtime.h>

#define BATCH   64
#define D_IN    512
#define D_OUT   512
#define GRID_N  100
#define NCHUNK  8
#define CHUNK   (D_IN / NCHUNK)   // 64
#define LN_EPS   1e-5f
#define GRID_EPS 1e-6f

// Scratch (allocation-free rule: __device__ globals)
__device__ int    g_idx_s[BATCH * D_IN];
__device__ float4 g_w_s[BATCH * D_IN];
__device__ float  g_partial[NCHUNK * BATCH * D_OUT];

// ---------------------------------------------------------------------------
// Kernel 1: LayerNorm + grid index + Bernstein basis weights
// one CTA per batch row, 512 threads (one per i)
// ---------------------------------------------------------------------------
__global__ __launch_bounds__(512) void prep_kernel(
    const float* __restrict__ x,
    const float* __restrict__ ln_w,
    const float* __restrict__ ln_b,
    const float* __restrict__ M)     // basis_matrix, row-major [j][k], 4x4
{
    const int b = blockIdx.x;
    const int i = threadIdx.x;

    __shared__ float red[16];
    __shared__ float sM[16];
    if (i < 16) sM[i] = M[i];

    float v = x[b * D_IN + i];

    // ---- block reduce: sum(x) ----
    float s = v;
    #pragma unroll
    for (int off = 16; off > 0; off >>= 1) s += __shfl_xor_sync(0xffffffffu, s, off);
    if ((i & 31) == 0) red[i >> 5] = s;
    __syncthreads();
    if (i < 32) {
        float r = (i < 16) ? red[i] : 0.0f;
        #pragma unroll
        for (int off = 8; off > 0; off >>= 1) r += __shfl_xor_sync(0xffffffffu, r, off);
        if (i == 0) red[0] = r;
    }
    __syncthreads();
    const float mean = red[0] * (1.0f / D_IN);
    __syncthreads();   // red[] reuse

    // ---- block reduce: sum((x-mean)^2) ----
    const float d = v - mean;
    s = d * d;
    #pragma unroll
    for (int off = 16; off > 0; off >>= 1) s += __shfl_xor_sync(0xffffffffu, s, off);
    if ((i & 31) == 0) red[i >> 5] = s;
    __syncthreads();
    if (i < 32) {
        float r = (i < 16) ? red[i] : 0.0f;
        #pragma unroll
        for (int off = 8; off > 0; off >>= 1) r += __shfl_xor_sync(0xffffffffu, r, off);
        if (i == 0) red[0] = r;
    }
    __syncthreads();
    const float var = red[0] * (1.0f / D_IN);

    // ---- normalize, clip, grid map ----
    float xn = d * rsqrtf(var + LN_EPS) * ln_w[i] + ln_b[i];
    xn = fminf(fmaxf(xn, -1.0f + GRID_EPS), 1.0f - GRID_EPS);
    xn = (xn + 1.0f) * 0.5f;
    const float scaled = xn * (float)GRID_N;
    int gi = (int)floorf(scaled);
    gi = max(0, min(gi, GRID_N - 1));
    const float t  = scaled - (float)gi;
    const float t2 = t * t;
    const float t3 = t2 * t;

    // basis_values[k] = sum_j t^j * M[j][k]
    float4 w;
    w.x = sM[0] + t * sM[4] + t2 * sM[8]  + t3 * sM[12];
    w.y = sM[1] + t * sM[5] + t2 * sM[9]  + t3 * sM[13];
    w.z = sM[2] + t * sM[6] + t2 * sM[10] + t3 * sM[14];
    w.w = sM[3] + t * sM[7] + t2 * sM[11] + t3 * sM[15];

    g_idx_s[b * D_IN + i] = gi;
    g_w_s  [b * D_IN + i] = w;
}

// ---------------------------------------------------------------------------
// Kernel 2: the gather + dot4 accumulation.
// grid = (BATCH, NCHUNK); blockIdx.x = b (fast) so all batches of the same
// i-chunk run concurrently -> L2 reuse of shared (i,g) slabs.
// thread = o; each thread does CHUNK float4 gathers.
// ---------------------------------------------------------------------------
__global__ __launch_bounds__(512) void gather_kernel(const float* __restrict__ poly)
{
    const int b     = blockIdx.x;
    const int chunk = blockIdx.y;
    const int o     = threadIdx.x;

    __shared__ int    sg[CHUNK];
    __shared__ float4 sw[CHUNK];
    const int base = b * D_IN + chunk * CHUNK;
    if (o < CHUNK) {
        sg[o] = g_idx_s[base + o];
        sw[o] = g_w_s  [base + o];
    }
    __syncthreads();

    // poly[i][o][g][k]: offset = i*(D_OUT*GRID_N*4) + o*(GRID_N*4) + g*4 + k
    const float* pbase = poly
        + (size_t)(chunk * CHUNK) * (size_t)(D_OUT * GRID_N * 4)
        + (size_t)o * (GRID_N * 4);

    float acc = 0.0f;
    #pragma unroll 8
    for (int ii = 0; ii < CHUNK; ii++) {
        const int    gi = sg[ii];
        const float4 w  = sw[ii];
        const float4 pv = *reinterpret_cast<const float4*>(
            pbase + (size_t)ii * (size_t)(D_OUT * GRID_N * 4) + gi * 4);
        acc += w.x * pv.x + w.y * pv.y + w.z * pv.z + w.w * pv.w;
    }

    g_partial[(chunk * BATCH + b) * D_OUT + o] = acc;
}

// ---------------------------------------------------------------------------
// Kernel 3: reduce partials over chunks (deterministic, no atomics)
// ---------------------------------------------------------------------------
__global__ void reduce_kernel(float* __restrict__ out)
{
    const int idx = blockIdx.x * blockDim.x + threadIdx.x;
    if (idx >= BATCH * D_OUT) return;
    float acc = 0.0f;
    #pragma unroll
    for (int c = 0; c < NCHUNK; c++)
        acc += g_partial[c * BATCH * D_OUT + idx];
    out[idx] = acc;
}

// ---------------------------------------------------------------------------
extern "C" void kernel_launch(void* const* d_in, const int* in_sizes, int n_in,
                              void* d_out, int out_size)
{
    const float* x    = (const float*)d_in[0];   // (64, 512)
    const float* poly = (const float*)d_in[1];   // (512, 512, 100, 4)
    const float* ln_w = (const float*)d_in[2];   // (512,)
    const float* ln_b = (const float*)d_in[3];   // (512,)
    const float* M    = (const float*)d_in[4];   // (4, 4)
    float* out = (float*)d_out;                  // (64, 512) fp32

    prep_kernel<<<BATCH, D_IN>>>(x, ln_w, ln_b, M);
    gather_kernel<<<dim3(BATCH, NCHUNK), D_OUT>>>(poly);
    reduce_kernel<<<(BATCH * D_OUT + 255) / 256, 256>>>(out);
}